// round 4
// baseline (speedup 1.0000x reference)
#include <cuda_runtime.h>

#define NB      8
#define CIN     96
#define COUT    192
#define STRIDE  4
#define TM      64
#define THREADS 128
#define APAD    97      // sA row stride in floats (odd*... : 8*97 mod 32 words = 8 -> conflict-free)
#define GRID    296     // 2 persistent blocks per SM on 148 SMs

__device__ int g_off[NB + 1];     // point offsets per batch
__device__ int g_winoff[NB + 1];  // window offsets per batch
__device__ int g_M;               // total windows

// ---------------------------------------------------------------------------
// Setup: prefix sums over the 8 lengths. Sniffs int32 vs int64 storage
// (int64 positive values ~131072 have a zero high word at index 1).
// Also writes lengths_down / offset_down to the tail of the output buffer.
// ---------------------------------------------------------------------------
__global__ void setup_kernel(const int* __restrict__ lenw, float* __restrict__ out) {
    if (threadIdx.x != 0 || blockIdx.x != 0) return;
    const bool is64 = (lenw[1] == 0);
    int off = 0, woff = 0;
    g_off[0] = 0; g_winoff[0] = 0;
    int nw[NB];
    for (int i = 0; i < NB; i++) {
        int L = is64 ? lenw[2 * i] : lenw[i];
        off += L;            g_off[i + 1] = off;
        nw[i] = (L + STRIDE - 1) / STRIDE;
        woff += nw[i];       g_winoff[i + 1] = woff;
    }
    g_M = woff;
    float* tail = out + (size_t)woff * 197;
    int c = 0;
    for (int i = 0; i < NB; i++) {
        tail[i] = (float)nw[i];
        c += nw[i];
        tail[NB + i] = (float)c;
    }
}

// ---------------------------------------------------------------------------
// Fused persistent kernel: per 64-window tile
//   phase 0: window metadata + coord/scores/batch pooling (tid < 64)
//   phase 1: feat mean-pool into smem sA[64][97]
//   phase 2: GEMM relu(sA @ sW + b) with packed fma.rn.f32x2
// W (96x192 fp32 = 73.7 KB) lives in smem for the block's whole lifetime.
// ---------------------------------------------------------------------------
extern __shared__ float smem[];

__global__ void __launch_bounds__(THREADS, 2) fused_kernel(
    const float* __restrict__ feat, const float* __restrict__ coord,
    const float* __restrict__ scores, const float* __restrict__ W,
    const float* __restrict__ bias, float* __restrict__ out)
{
    float* sW    = smem;                    // 96*192 = 18432 floats
    float* sA    = sW + CIN * COUT;         // 64*97  = 6208 floats
    float* sBias = sA + TM * APAD;          // 192 floats
    float* sInv  = sBias + COUT;            // 64 floats
    int*   sStart = (int*)(sInv + TM);      // 64 ints
    int*   sCnt   = sStart + TM;            // 64 ints

    const int tid = threadIdx.x;
    const int M   = g_M;

    // Load W + bias into smem once per (persistent) block
    {
        const float4* W4 = (const float4*)W;
        float4* sW4 = (float4*)sW;
        for (int i = tid; i < (CIN * COUT) / 4; i += THREADS) sW4[i] = W4[i];
        for (int i = tid; i < COUT; i += THREADS) sBias[i] = bias[i];
    }

    const int numTiles = (M + TM - 1) / TM;
    const size_t coord_base = (size_t)M * COUT;  // M*192
    const size_t batch_base = (size_t)M * 195;
    const size_t score_base = (size_t)M * 196;

    const int tx = tid & 15;   // column group: pairs 2*tx + 32*j, j<6
    const int ty = tid >> 4;   // row group:    rows ty*8 + i,     i<8

    for (int tile = blockIdx.x; tile < numTiles; tile += GRID) {
        const int w0 = tile * TM;
        __syncthreads();  // previous tile's GEMM done reading sA / first-iter W load done

        // -------- phase 0: metadata + small pooled outputs --------
        if (tid < TM) {
            int w = w0 + tid;
            if (w < M) {
                int b = 0;
                #pragma unroll
                for (int i = 1; i <= NB; i++) if (w >= g_winoff[i]) b = i;
                int start = g_off[b] + (w - g_winoff[b]) * STRIDE;
                int cnt   = min(STRIDE, g_off[b + 1] - start);
                float inv = 1.0f / (float)cnt;
                sStart[tid] = start; sCnt[tid] = cnt; sInv[tid] = inv;

                float cx = 0.f, cy = 0.f, cz = 0.f, sc = 0.f;
                for (int j = 0; j < cnt; j++) {
                    const float* cp = coord + (size_t)(start + j) * 3;
                    cx += cp[0]; cy += cp[1]; cz += cp[2];
                    sc += scores[start + j];
                }
                float* co = out + coord_base + (size_t)w * 3;
                co[0] = cx * inv; co[1] = cy * inv; co[2] = cz * inv;
                out[batch_base + w] = (float)b;
                out[score_base + w] = sc * inv;
            } else {
                sStart[tid] = 0; sCnt[tid] = 0; sInv[tid] = 0.f;
            }
        }
        __syncthreads();

        // -------- phase 1: feat mean-pool into sA --------
        // 64 windows x 24 float4-chunks = 1536 tasks; coalesced within rows
        for (int task = tid; task < TM * 24; task += THREADS) {
            int w = task / 24;
            int c = task - w * 24;
            int st = sStart[w], cn = sCnt[w];
            float4 acc = make_float4(0.f, 0.f, 0.f, 0.f);
            const float* base = feat + (size_t)st * CIN + c * 4;
            for (int j = 0; j < cn; j++) {
                float4 v = *(const float4*)(base + j * CIN);
                acc.x += v.x; acc.y += v.y; acc.z += v.z; acc.w += v.w;
            }
            float inv = sInv[w];
            float* dst = sA + w * APAD + c * 4;
            dst[0] = acc.x * inv; dst[1] = acc.y * inv;
            dst[2] = acc.z * inv; dst[3] = acc.w * inv;
        }
        __syncthreads();

        // -------- phase 2: GEMM (packed f32x2 FFMA) --------
        unsigned long long acc[8][6];
        #pragma unroll
        for (int i = 0; i < 8; i++)
            #pragma unroll
            for (int j = 0; j < 6; j++) acc[i][j] = 0ull;

        const float* Ab = sA + (ty * 8) * APAD;
        const float* Bb = sW + 2 * tx;

        #pragma unroll 4
        for (int k = 0; k < CIN; k++) {
            unsigned long long a2[8];
            #pragma unroll
            for (int i = 0; i < 8; i++) {
                unsigned int au = __float_as_uint(Ab[i * APAD + k]);
                asm("mov.b64 %0, {%1, %1};" : "=l"(a2[i]) : "r"(au));
            }
            unsigned long long b2[6];
            const float* Bk = Bb + k * COUT;
            #pragma unroll
            for (int j = 0; j < 6; j++)
                b2[j] = *(const unsigned long long*)(Bk + 32 * j);  // LDS.64, conflict-free
            #pragma unroll
            for (int i = 0; i < 8; i++)
                #pragma unroll
                for (int j = 0; j < 6; j++)
                    asm("fma.rn.f32x2 %0, %1, %2, %0;"
                        : "+l"(acc[i][j]) : "l"(a2[i]), "l"(b2[j]));
        }

        // -------- epilogue: bias + relu + float2 stores --------
        #pragma unroll
        for (int i = 0; i < 8; i++) {
            int w = w0 + ty * 8 + i;
            if (w < M) {
                float* o = out + (size_t)w * COUT + 2 * tx;
                #pragma unroll
                for (int j = 0; j < 6; j++) {
                    unsigned int lo, hi;
                    asm("mov.b64 {%0, %1}, %2;" : "=r"(lo), "=r"(hi) : "l"(acc[i][j]));
                    float2 r;
                    r.x = fmaxf(__uint_as_float(lo) + sBias[32 * j + 2 * tx], 0.f);
                    r.y = fmaxf(__uint_as_float(hi) + sBias[32 * j + 2 * tx + 1], 0.f);
                    *(float2*)(o + 32 * j) = r;
                }
            }
        }
    }
}

// ---------------------------------------------------------------------------
extern "C" void kernel_launch(void* const* d_in, const int* in_sizes, int n_in,
                              void* d_out, int out_size) {
    const float* feat    = (const float*)d_in[0];
    const float* coord   = (const float*)d_in[1];
    const float* scores  = (const float*)d_in[2];
    const float* W       = (const float*)d_in[3];
    const float* bias    = (const float*)d_in[4];
    const int*   lengths = (const int*)d_in[5];   // dtype sniffed on device
    float* out = (float*)d_out;

    const size_t smem_bytes =
        (size_t)(CIN * COUT + TM * APAD + COUT + TM) * sizeof(float)
        + (size_t)TM * 2 * sizeof(int);   // = 100,096 B

    cudaFuncSetAttribute(fused_kernel,
                         cudaFuncAttributeMaxDynamicSharedMemorySize,
                         (int)smem_bytes);

    setup_kernel<<<1, 1>>>(lengths, out);
    fused_kernel<<<GRID, THREADS, smem_bytes>>>(feat, coord, scores, W, bias, out);
}

// round 7
// speedup vs baseline: 1.0133x; 1.0133x over previous
#include <cuda_runtime.h>

#define NB      8
#define CIN     96
#define COUT    192
#define STRIDE  4
#define TM      64
#define THREADS 128
#define APAD    97      // sA row stride in floats (odd*... : 8*97 mod 32 words = 8 -> conflict-free)
#define GRID    296     // 2 persistent blocks per SM on 148 SMs

__device__ int g_off[NB + 1];     // point offsets per batch
__device__ int g_winoff[NB + 1];  // window offsets per batch
__device__ int g_M;               // total windows

// ---------------------------------------------------------------------------
// Setup: prefix sums over the 8 lengths. Sniffs int32 vs int64 storage
// (int64 positive values ~131072 have a zero high word at index 1).
// Also writes lengths_down / offset_down to the tail of the output buffer.
// ---------------------------------------------------------------------------
__global__ void setup_kernel(const int* __restrict__ lenw, float* __restrict__ out) {
    if (threadIdx.x != 0 || blockIdx.x != 0) return;
    const bool is64 = (lenw[1] == 0);
    int off = 0, woff = 0;
    g_off[0] = 0; g_winoff[0] = 0;
    int nw[NB];
    for (int i = 0; i < NB; i++) {
        int L = is64 ? lenw[2 * i] : lenw[i];
        off += L;            g_off[i + 1] = off;
        nw[i] = (L + STRIDE - 1) / STRIDE;
        woff += nw[i];       g_winoff[i + 1] = woff;
    }
    g_M = woff;
    float* tail = out + (size_t)woff * 197;
    int c = 0;
    for (int i = 0; i < NB; i++) {
        tail[i] = (float)nw[i];
        c += nw[i];
        tail[NB + i] = (float)c;
    }
}

// ---------------------------------------------------------------------------
// Fused persistent kernel: per 64-window tile
//   phase 0: window metadata + coord/scores/batch pooling (tid < 64)
//   phase 1: feat mean-pool into smem sA[64][97]
//   phase 2: GEMM relu(sA @ sW + b) with packed fma.rn.f32x2
// W (96x192 fp32 = 73.7 KB) lives in smem for the block's whole lifetime.
// ---------------------------------------------------------------------------
extern __shared__ float smem[];

__global__ void __launch_bounds__(THREADS, 2) fused_kernel(
    const float* __restrict__ feat, const float* __restrict__ coord,
    const float* __restrict__ scores, const float* __restrict__ W,
    const float* __restrict__ bias, float* __restrict__ out)
{
    float* sW    = smem;                    // 96*192 = 18432 floats
    float* sA    = sW + CIN * COUT;         // 64*97  = 6208 floats
    float* sBias = sA + TM * APAD;          // 192 floats
    float* sInv  = sBias + COUT;            // 64 floats
    int*   sStart = (int*)(sInv + TM);      // 64 ints
    int*   sCnt   = sStart + TM;            // 64 ints

    const int tid = threadIdx.x;
    const int M   = g_M;

    // Load W + bias into smem once per (persistent) block
    {
        const float4* W4 = (const float4*)W;
        float4* sW4 = (float4*)sW;
        for (int i = tid; i < (CIN * COUT) / 4; i += THREADS) sW4[i] = W4[i];
        for (int i = tid; i < COUT; i += THREADS) sBias[i] = bias[i];
    }

    const int numTiles = (M + TM - 1) / TM;
    const size_t coord_base = (size_t)M * COUT;  // M*192
    const size_t batch_base = (size_t)M * 195;
    const size_t score_base = (size_t)M * 196;

    const int tx = tid & 15;   // column group: pairs 2*tx + 32*j, j<6
    const int ty = tid >> 4;   // row group:    rows ty*8 + i,     i<8

    for (int tile = blockIdx.x; tile < numTiles; tile += GRID) {
        const int w0 = tile * TM;
        __syncthreads();  // previous tile's GEMM done reading sA / first-iter W load done

        // -------- phase 0: metadata + small pooled outputs --------
        if (tid < TM) {
            int w = w0 + tid;
            if (w < M) {
                int b = 0;
                #pragma unroll
                for (int i = 1; i <= NB; i++) if (w >= g_winoff[i]) b = i;
                int start = g_off[b] + (w - g_winoff[b]) * STRIDE;
                int cnt   = min(STRIDE, g_off[b + 1] - start);
                float inv = 1.0f / (float)cnt;
                sStart[tid] = start; sCnt[tid] = cnt; sInv[tid] = inv;

                float cx = 0.f, cy = 0.f, cz = 0.f, sc = 0.f;
                for (int j = 0; j < cnt; j++) {
                    const float* cp = coord + (size_t)(start + j) * 3;
                    cx += cp[0]; cy += cp[1]; cz += cp[2];
                    sc += scores[start + j];
                }
                float* co = out + coord_base + (size_t)w * 3;
                co[0] = cx * inv; co[1] = cy * inv; co[2] = cz * inv;
                out[batch_base + w] = (float)b;
                out[score_base + w] = sc * inv;
            } else {
                sStart[tid] = 0; sCnt[tid] = 0; sInv[tid] = 0.f;
            }
        }
        __syncthreads();

        // -------- phase 1: feat mean-pool into sA --------
        // 64 windows x 24 float4-chunks = 1536 tasks; coalesced within rows
        for (int task = tid; task < TM * 24; task += THREADS) {
            int w = task / 24;
            int c = task - w * 24;
            int st = sStart[w], cn = sCnt[w];
            float4 acc = make_float4(0.f, 0.f, 0.f, 0.f);
            const float* base = feat + (size_t)st * CIN + c * 4;
            for (int j = 0; j < cn; j++) {
                float4 v = *(const float4*)(base + j * CIN);
                acc.x += v.x; acc.y += v.y; acc.z += v.z; acc.w += v.w;
            }
            float inv = sInv[w];
            float* dst = sA + w * APAD + c * 4;
            dst[0] = acc.x * inv; dst[1] = acc.y * inv;
            dst[2] = acc.z * inv; dst[3] = acc.w * inv;
        }
        __syncthreads();

        // -------- phase 2: GEMM (packed f32x2 FFMA) --------
        unsigned long long acc[8][6];
        #pragma unroll
        for (int i = 0; i < 8; i++)
            #pragma unroll
            for (int j = 0; j < 6; j++) acc[i][j] = 0ull;

        const float* Ab = sA + (ty * 8) * APAD;
        const float* Bb = sW + 2 * tx;

        #pragma unroll 4
        for (int k = 0; k < CIN; k++) {
            unsigned long long a2[8];
            #pragma unroll
            for (int i = 0; i < 8; i++) {
                unsigned int au = __float_as_uint(Ab[i * APAD + k]);
                asm("mov.b64 %0, {%1, %1};" : "=l"(a2[i]) : "r"(au));
            }
            unsigned long long b2[6];
            const float* Bk = Bb + k * COUT;
            #pragma unroll
            for (int j = 0; j < 6; j++)
                b2[j] = *(const unsigned long long*)(Bk + 32 * j);  // LDS.64, conflict-free
            #pragma unroll
            for (int i = 0; i < 8; i++)
                #pragma unroll
                for (int j = 0; j < 6; j++)
                    asm("fma.rn.f32x2 %0, %1, %2, %0;"
                        : "+l"(acc[i][j]) : "l"(a2[i]), "l"(b2[j]));
        }

        // -------- epilogue: bias + relu + float2 stores --------
        #pragma unroll
        for (int i = 0; i < 8; i++) {
            int w = w0 + ty * 8 + i;
            if (w < M) {
                float* o = out + (size_t)w * COUT + 2 * tx;
                #pragma unroll
                for (int j = 0; j < 6; j++) {
                    unsigned int lo, hi;
                    asm("mov.b64 {%0, %1}, %2;" : "=r"(lo), "=r"(hi) : "l"(acc[i][j]));
                    float2 r;
                    r.x = fmaxf(__uint_as_float(lo) + sBias[32 * j + 2 * tx], 0.f);
                    r.y = fmaxf(__uint_as_float(hi) + sBias[32 * j + 2 * tx + 1], 0.f);
                    *(float2*)(o + 32 * j) = r;
                }
            }
        }
    }
}

// ---------------------------------------------------------------------------
extern "C" void kernel_launch(void* const* d_in, const int* in_sizes, int n_in,
                              void* d_out, int out_size) {
    const float* feat    = (const float*)d_in[0];
    const float* coord   = (const float*)d_in[1];
    const float* scores  = (const float*)d_in[2];
    const float* W       = (const float*)d_in[3];
    const float* bias    = (const float*)d_in[4];
    const int*   lengths = (const int*)d_in[5];   // dtype sniffed on device
    float* out = (float*)d_out;

    const size_t smem_bytes =
        (size_t)(CIN * COUT + TM * APAD + COUT + TM) * sizeof(float)
        + (size_t)TM * 2 * sizeof(int);   // = 100,096 B

    cudaFuncSetAttribute(fused_kernel,
                         cudaFuncAttributeMaxDynamicSharedMemorySize,
                         (int)smem_bytes);

    setup_kernel<<<1, 1>>>(lengths, out);
    fused_kernel<<<GRID, THREADS, smem_bytes>>>(feat, coord, scores, W, bias, out);
}